// round 3
// baseline (speedup 1.0000x reference)
#include <cuda_runtime.h>
#include <cstdint>

#define NB 512
#define ND 256
#define NC 10

// ---------------------------------------------------------------------------
// packed fp32x2 helpers
// ---------------------------------------------------------------------------
typedef unsigned long long ps_t;

__device__ __forceinline__ ps_t pk2(float lo, float hi) {
    ps_t o; asm("mov.b64 %0,{%1,%2};" : "=l"(o) : "f"(lo), "f"(hi)); return o;
}
__device__ __forceinline__ void up2(ps_t a, float& lo, float& hi) {
    asm("mov.b64 {%0,%1},%2;" : "=f"(lo), "=f"(hi) : "l"(a));
}
__device__ __forceinline__ ps_t fma2(ps_t a, ps_t b, ps_t c) {
    ps_t d; asm("fma.rn.f32x2 %0,%1,%2,%3;" : "=l"(d) : "l"(a), "l"(b), "l"(c)); return d;
}
__device__ __forceinline__ ps_t add2(ps_t a, ps_t b) {
    ps_t d; asm("add.rn.f32x2 %0,%1,%2;" : "=l"(d) : "l"(a), "l"(b)); return d;
}
__device__ __forceinline__ ps_t relu2(ps_t a) {
    float l, h; up2(a, l, h);
    return pk2(fmaxf(l, 0.f), fmaxf(h, 0.f));
}

// packed weights: [0:10) w1, [10:20) b1, [20:110) w2[c*9+kh*3+kw], [110] b2
__constant__ ps_t c_pack[111];
__device__ ps_t g_pack[111];
__device__ float g_part[512 * 4];
__device__ float g_rs2[NB * ND];   // [bi][i][hb] : pair-packed row sums
__device__ float g_cs2[NB * ND];   // [bi][j][hb]

// ---------------------------------------------------------------------------
// Kernel 1: per-batch row/col sums (streaming, HBM-bound) + weight packing
// grid = 512 (one block per batch), 256 threads
// ---------------------------------------------------------------------------
__global__ void __launch_bounds__(256) ksums(const float* __restrict__ x,
                                             const float* __restrict__ w1,
                                             const float* __restrict__ b1,
                                             const float* __restrict__ w2,
                                             const float* __restrict__ b2) {
    const int b = blockIdx.x;
    const int t = threadIdx.x;
    const int w = t >> 5;
    const int l = t & 31;
    const int bi = b >> 1;
    const int hb = b & 1;

    if (b == 0) {   // weight packing (tiny)
        if (t < 10) { g_pack[t] = pk2(w1[t], w1[t]); g_pack[10 + t] = pk2(b1[t], b1[t]); }
        if (t < 90) g_pack[20 + t] = pk2(w2[t], w2[t]);
        if (t == 0) g_pack[110] = pk2(b2[0], b2[0]);
    }

    __shared__ float scs[8 * 256];
    const float4* __restrict__ xb =
        reinterpret_cast<const float4*>(x + (size_t)b * (ND * ND));

    float ca[8];
#pragma unroll
    for (int k = 0; k < 8; ++k) ca[k] = 0.f;

    const int i0 = 32 * w;
    for (int i = i0; i < i0 + 32; ++i) {
        float4 v0 = xb[i * 64 + 2 * l];
        float4 v1 = xb[i * 64 + 2 * l + 1];
        ca[0] += v0.x; ca[1] += v0.y; ca[2] += v0.z; ca[3] += v0.w;
        ca[4] += v1.x; ca[5] += v1.y; ca[6] += v1.z; ca[7] += v1.w;
        float rsum = (v0.x + v0.y) + (v0.z + v0.w) + (v1.x + v1.y) + (v1.z + v1.w);
#pragma unroll
        for (int o = 16; o; o >>= 1) rsum += __shfl_xor_sync(0xffffffffu, rsum, o);
        if (l == 0) g_rs2[bi * 512 + i * 2 + hb] = rsum;
    }
#pragma unroll
    for (int k = 0; k < 8; ++k) scs[w * 256 + 8 * l + k] = ca[k];
    __syncthreads();
    float c = 0.f;
#pragma unroll
    for (int ww = 0; ww < 8; ++ww) c += scs[ww * 256 + t];
    g_cs2[bi * 512 + t * 2 + hb] = c;
}

// ---------------------------------------------------------------------------
// tap: 10-ch generate + 3-row accumulate for one conv column e
// ---------------------------------------------------------------------------
__device__ __forceinline__ void tap2(ps_t t2, int e, ps_t& A0, ps_t& A1, ps_t& A2) {
#pragma unroll
    for (int c = 0; c < NC; ++c) {
        ps_t g = relu2(fma2(c_pack[c], t2, c_pack[10 + c]));
        A0 = fma2(c_pack[20 + c * 9 + 0 + e], g, A0);
        A1 = fma2(c_pack[20 + c * 9 + 3 + e], g, A1);
        A2 = fma2(c_pack[20 + c * 9 + 6 + e], g, A2);
    }
}

// ---------------------------------------------------------------------------
// Kernel 2: band conv over a row-half, packed over batch pair.
// grid = 512: block = (bi = bid>>1, h = bid&1); rows [128h, 128h+128).
// Warp -> column range rotated by bid (SMSP load balancing across blocks).
// Produces partial v, then fc1 partial dot products into g_part[bid*4+k].
// ---------------------------------------------------------------------------
__global__ void __launch_bounds__(256) kband(const float* __restrict__ fc1w) {
    const int bid = blockIdx.x;
    const int bi = bid >> 1;
    const int h = bid & 1;
    const int rlo = h << 7;
    const int rhi = rlo + 128;

    const int t = threadIdx.x;
    const int w = t >> 5;
    const int lane = t & 31;

    __shared__ ps_t srs2[ND];
    __shared__ ps_t scs2[ND];
    __shared__ ps_t srow2[8][128];
    __shared__ float sred[8][4];

    srs2[t] = ((const ps_t*)g_rs2)[bi * 256 + t];
    scs2[t] = ((const ps_t*)g_cs2)[bi * 256 + t];
#pragma unroll
    for (int k = 0; k < 4; ++k) ((ps_t*)srow2)[t + 256 * k] = 0ULL;
    __syncthreads();

    // rotated, SMSP-balanced column-range assignment
    const int q = ((w & 3) + bid) & 3;
    const int r = (w < 4) ? q : 7 - q;
    const int j = 32 * r + lane;

    const bool vm1 = (j >= 1);
    const bool vp1 = (j <= 254);
    const ps_t csm = vm1 ? scs2[j - 1] : 0ULL;
    const ps_t cs0 = scs2[j];
    const ps_t csp = vp1 ? scs2[j + 1] : 0ULL;

    const ps_t b2v = c_pack[110];
    float b2f, b2d; up2(b2v, b2f, b2d);
    const float c0 = fmaxf(b2f, 0.f);

    ps_t pend1 = 0ULL, a0last = 0ULL, colacc = 0ULL;
    int p0 = 32 * r - 3;
    if (p0 < rlo - 1) p0 = rlo - 1;
    if (p0 < 0) p0 = 0;

#pragma unroll 2
    for (int p = p0; p <= rhi; ++p) {
        ps_t A0 = 0ULL, A1 = 0ULL, A2 = 0ULL;
        if (p < 256) {
            const ps_t rsp = srs2[p];
            if (vm1 && (j - 1) <= p) tap2(add2(rsp, csm), 0, A0, A1, A2);
            if ((j) <= p)            tap2(add2(rsp, cs0), 1, A0, A1, A2);
            if (vp1 && (j + 1) <= p) tap2(add2(rsp, csp), 2, A0, A1, A2);
        }
        if (p > rlo) {   // emit row i = p-1  (rlo <= i < rhi)
            ps_t y = relu2(add2(add2(pend1, A2), b2v));
            ps_t yc = (j <= p + 1) ? y : 0ULL;
            colacc = add2(colacc, yc);
            ps_t rsum = yc;
#pragma unroll
            for (int o = 16; o; o >>= 1)
                rsum = add2(rsum, __shfl_xor_sync(0xffffffffu, rsum, o));
            if (lane == 0) srow2[r][p - 1 - rlo] = rsum;
        }
        pend1 = add2(A1, a0last);
        a0last = A0;
    }
    __syncthreads();

    // partial v for this half
    ps_t rowtot = 0ULL;
    const bool inhalf = (j >= rlo) && (j < rhi);
    if (inhalf) {
#pragma unroll
        for (int k = 0; k < 8; ++k) rowtot = add2(rowtot, srow2[k][j - rlo]);
    }
    const int rn = inhalf ? ((253 - j) > 0 ? (253 - j) : 0) : 0;
    int cc = j - 2 - rlo;
    cc = (cc < 0) ? 0 : (cc > 128 ? 128 : cc);
    const float corr = c0 * (float)(rn + cc);

    const ps_t v2 = add2(add2(rowtot, colacc), pk2(corr, corr));
    float v0f, v1f; up2(v2, v0f, v1f);

    // fc1 partial dot products
    const int b0 = 2 * bi;
    float pk4[4];
#pragma unroll
    for (int k = 0; k < 4; ++k) {
        const float* wrow = fc1w + (size_t)k * 131072 + b0 * 256 + j;
        pk4[k] = wrow[0] * v0f + wrow[256] * v1f;
    }
#pragma unroll
    for (int o = 16; o; o >>= 1) {
#pragma unroll
        for (int k = 0; k < 4; ++k)
            pk4[k] += __shfl_xor_sync(0xffffffffu, pk4[k], o);
    }
    if (lane == 0) {
#pragma unroll
        for (int k = 0; k < 4; ++k) sred[w][k] = pk4[k];
    }
    __syncthreads();
    if (t < 4) {
        float s = 0.f;
#pragma unroll
        for (int ww = 0; ww < 8; ++ww) s += sred[ww][t];
        g_part[bid * 4 + t] = s;
    }
}

// ---------------------------------------------------------------------------
// Kernel 3: reduce 512x4 partials + fc2
// ---------------------------------------------------------------------------
__global__ void kfc2(const float* __restrict__ fc1b,
                     const float* __restrict__ fc2w,
                     const float* __restrict__ fc2b,
                     float* __restrict__ out) {
    __shared__ float sh[4];
    const int w = threadIdx.x >> 5;
    const int lane = threadIdx.x & 31;
    float s = 0.f;
    for (int i = lane; i < 512; i += 32) s += g_part[i * 4 + w];
#pragma unroll
    for (int o = 16; o; o >>= 1) s += __shfl_xor_sync(0xffffffffu, s, o);
    if (lane == 0) sh[w] = s;
    __syncthreads();
    if (threadIdx.x == 0) {
        float h0 = fmaxf(sh[0] + fc1b[0], 0.f);
        float h1 = fmaxf(sh[1] + fc1b[1], 0.f);
        float h2 = fmaxf(sh[2] + fc1b[2], 0.f);
        float h3 = fmaxf(sh[3] + fc1b[3], 0.f);
        out[0] = fc2w[0] * h0 + fc2w[1] * h1 + fc2w[2] * h2 + fc2w[3] * h3 + fc2b[0];
        out[1] = fc2w[4] * h0 + fc2w[5] * h1 + fc2w[6] * h2 + fc2w[7] * h3 + fc2b[1];
    }
}

// ---------------------------------------------------------------------------
extern "C" void kernel_launch(void* const* d_in, const int* in_sizes, int n_in,
                              void* d_out, int out_size) {
    const float* x    = (const float*)d_in[0];
    const float* w1   = (const float*)d_in[1];
    const float* b1   = (const float*)d_in[2];
    const float* w2   = (const float*)d_in[3];
    const float* b2   = (const float*)d_in[4];
    const float* fc1w = (const float*)d_in[5];
    const float* fc1b = (const float*)d_in[6];
    const float* fc2w = (const float*)d_in[7];
    const float* fc2b = (const float*)d_in[8];

    ksums<<<NB, 256>>>(x, w1, b1, w2, b2);

    void* gp = nullptr;
    cudaGetSymbolAddress(&gp, g_pack);
    cudaMemcpyToSymbolAsync(c_pack, gp, 111 * sizeof(ps_t), 0,
                            cudaMemcpyDeviceToDevice, 0);

    kband<<<512, 256>>>(fc1w);
    kfc2<<<1, 128>>>(fc1b, fc2w, fc2b, (float*)d_out);
}

// round 4
// speedup vs baseline: 1.1839x; 1.1839x over previous
#include <cuda_runtime.h>
#include <cstdint>

#define NB 512
#define ND 256
#define NC 10

// ---------------------------------------------------------------------------
// packed fp32x2 helpers
// ---------------------------------------------------------------------------
typedef unsigned long long ps_t;

__device__ __forceinline__ ps_t pk2(float lo, float hi) {
    ps_t o; asm("mov.b64 %0,{%1,%2};" : "=l"(o) : "f"(lo), "f"(hi)); return o;
}
__device__ __forceinline__ void up2(ps_t a, float& lo, float& hi) {
    asm("mov.b64 {%0,%1},%2;" : "=f"(lo), "=f"(hi) : "l"(a));
}
__device__ __forceinline__ ps_t fma2(ps_t a, ps_t b, ps_t c) {
    ps_t d; asm("fma.rn.f32x2 %0,%1,%2,%3;" : "=l"(d) : "l"(a), "l"(b), "l"(c)); return d;
}
__device__ __forceinline__ ps_t add2(ps_t a, ps_t b) {
    ps_t d; asm("add.rn.f32x2 %0,%1,%2;" : "=l"(d) : "l"(a), "l"(b)); return d;
}
__device__ __forceinline__ ps_t relu2(ps_t a) {
    float l, h; up2(a, l, h);
    return pk2(fmaxf(l, 0.f), fmaxf(h, 0.f));
}

// packed weights: [0:10) w1, [10:20) b1, [20:110) w2[c*9+kh*3+kw], [110] b2
__constant__ ps_t c_pack[111];
__device__ ps_t g_pack[111];
__device__ float g_part[256 * 4];
__device__ float g_rs2[NB * ND];   // [pair][i][hb]
__device__ float g_cs2[NB * ND];   // [pair][j][hb]

// ---------------------------------------------------------------------------
// Kernel 1: per-batch row/col sums. grid=512 (block per batch), 256 threads.
// Two-phase: load loop writes row partials to smem (no serial shfl chains
// blocking the LDG stream), then transpose-reduce.
// ---------------------------------------------------------------------------
__global__ void __launch_bounds__(256) ksums(const float* __restrict__ x,
                                             const float* __restrict__ w1,
                                             const float* __restrict__ b1,
                                             const float* __restrict__ w2,
                                             const float* __restrict__ b2) {
    const int b = blockIdx.x;
    const int t = threadIdx.x;
    const int w = t >> 5;
    const int l = t & 31;
    const int bi = b >> 1;
    const int hb = b & 1;

    if (b == 0) {   // weight packing (tiny)
        if (t < 10) { g_pack[t] = pk2(w1[t], w1[t]); g_pack[10 + t] = pk2(b1[t], b1[t]); }
        if (t < 90) g_pack[20 + t] = pk2(w2[t], w2[t]);
        if (t == 0) g_pack[110] = pk2(b2[0], b2[0]);
    }

    __shared__ float srp[8][32][33];   // [warp][row-in-chunk][lane] padded
    __shared__ float scs[8][256];

    const float4* __restrict__ xb =
        reinterpret_cast<const float4*>(x + (size_t)b * (ND * ND));

    float ca[8];
#pragma unroll
    for (int k = 0; k < 8; ++k) ca[k] = 0.f;

#pragma unroll 4
    for (int ri = 0; ri < 32; ++ri) {
        const int i = 32 * w + ri;
        float4 v0 = xb[i * 64 + 2 * l];
        float4 v1 = xb[i * 64 + 2 * l + 1];
        ca[0] += v0.x; ca[1] += v0.y; ca[2] += v0.z; ca[3] += v0.w;
        ca[4] += v1.x; ca[5] += v1.y; ca[6] += v1.z; ca[7] += v1.w;
        srp[w][ri][l] = (v0.x + v0.y) + (v0.z + v0.w) + (v1.x + v1.y) + (v1.z + v1.w);
    }
#pragma unroll
    for (int k = 0; k < 8; ++k) scs[w][8 * l + k] = ca[k];
    __syncthreads();

    // row reduce: thread t owns row t (conflict-free via 33-pad)
    {
        float s = 0.f;
        const int ww = t >> 5, r = t & 31;
#pragma unroll
        for (int l2 = 0; l2 < 32; ++l2) s += srp[ww][r][l2];
        g_rs2[bi * 512 + t * 2 + hb] = s;
    }
    // col reduce
    {
        float c = 0.f;
#pragma unroll
        for (int ww = 0; ww < 8; ++ww) c += scs[ww][t];
        g_cs2[bi * 512 + t * 2 + hb] = c;
    }
}

// ---------------------------------------------------------------------------
// tap: 10-ch generate + 3-row accumulate for one conv column e
// ---------------------------------------------------------------------------
__device__ __forceinline__ void tap2(ps_t t2, int e, ps_t& A0, ps_t& A1, ps_t& A2) {
#pragma unroll
    for (int c = 0; c < NC; ++c) {
        ps_t g = relu2(fma2(c_pack[c], t2, c_pack[10 + c]));
        A0 = fma2(c_pack[20 + c * 9 + 0 + e], g, A0);
        A1 = fma2(c_pack[20 + c * 9 + 3 + e], g, A1);
        A2 = fma2(c_pack[20 + c * 9 + 6 + e], g, A2);
    }
}

// ---------------------------------------------------------------------------
// per-column band sweep: accumulates y[i,q]*(W_k[i]+W_k[q]) directly into acc
// ---------------------------------------------------------------------------
__device__ __forceinline__ void sweep_col(
    int q, int qb,
    const ps_t* __restrict__ prs, const ps_t* __restrict__ pcs,
    const ps_t (*__restrict__ pW)[4],
    ps_t b2v, float c0, ps_t acc[4]) {

    ps_t wj[4];
#pragma unroll
    for (int k = 0; k < 4; ++k) wj[k] = pW[q][k];

    const bool vm = (q >= 1);
    const bool vp = (q <= 254);
    const ps_t csm = vm ? pcs[q - 1] : 0ULL;
    const ps_t cs0 = pcs[q];
    const ps_t csp = vp ? pcs[q + 1] : 0ULL;

    ps_t pend1 = 0ULL, a0last = 0ULL;
    int p0 = qb - 3; if (p0 < 0) p0 = 0;

    for (int p = p0; p < ND; ++p) {
        const ps_t rsp = prs[p];
        ps_t A0 = 0ULL, A1 = 0ULL, A2 = 0ULL;
        if (vm && (q - 1) <= p) tap2(add2(rsp, csm), 0, A0, A1, A2);
        if (q <= p)             tap2(add2(rsp, cs0), 1, A0, A1, A2);
        if (vp && (q + 1) <= p) tap2(add2(rsp, csp), 2, A0, A1, A2);

        if (p >= 1) {
            ps_t y = relu2(add2(add2(pend1, A2), b2v));
            ps_t yc = (q <= p + 1) ? y : 0ULL;
            const ps_t* w4 = pW[p - 1];
#pragma unroll
            for (int k = 0; k < 4; ++k)
                acc[k] = fma2(yc, add2(w4[k], wj[k]), acc[k]);
        }
        pend1 = add2(A1, a0last);
        a0last = A0;
    }
    // epilogue: i = 255 (phantom p = 256, A2 = 0)
    {
        ps_t y = relu2(add2(pend1, b2v));   // q <= 256+1 always: no mask needed
        const ps_t* w4 = pW[ND - 1];
#pragma unroll
        for (int k = 0; k < 4; ++k)
            acc[k] = fma2(y, add2(w4[k], wj[k]), acc[k]);
    }
    // constant-region correction for this column index q (as row i and col j)
    const int rn = (253 - q) > 0 ? (253 - q) : 0;
    const int cn = (q - 2) > 0 ? (q - 2) : 0;
    const float cf = c0 * (float)(rn + cn);
    const ps_t c2 = pk2(cf, cf);
#pragma unroll
    for (int k = 0; k < 4; ++k) acc[k] = fma2(c2, wj[k], acc[k]);
}

// ---------------------------------------------------------------------------
// Kernel 2: band conv + fused fc1. grid=128, 256 threads.
// Block handles 2 batch-pairs (warpgroup wg = pair). Thread owns the column
// PAIR (q, 255-q): per-lane trip count is a constant 263 — perfect balance.
// ---------------------------------------------------------------------------
__global__ void __launch_bounds__(256) kband(const float* __restrict__ fc1w) {
    const int t = threadIdx.x;
    const int w = t >> 5;
    const int lane = t & 31;
    const int wg = w >> 2;     // 0/1: which batch pair
    const int ww = w & 3;      // warp within group

    __shared__ ps_t srs[2][ND];
    __shared__ ps_t scs[2][ND];
    __shared__ ps_t sW[2][ND][4];   // [pair][i][k] packed fc1 weights
    __shared__ ps_t sred[8][4];

    for (int idx = t; idx < 512; idx += 256) {
        const int g2 = idx >> 8, i = idx & 255;
        const int pr = 2 * blockIdx.x + g2;
        srs[g2][i] = ((const ps_t*)g_rs2)[pr * 256 + i];
        scs[g2][i] = ((const ps_t*)g_cs2)[pr * 256 + i];
    }
    for (int idx = t; idx < 2048; idx += 256) {
        const int g2 = idx >> 10, rem = idx & 1023;
        const int i = rem >> 2, k = rem & 3;
        const int bb = 2 * (2 * blockIdx.x + g2);
        sW[g2][i][k] = pk2(fc1w[(size_t)k * 131072 + bb * 256 + i],
                           fc1w[(size_t)k * 131072 + (bb + 1) * 256 + i]);
    }
    __syncthreads();

    const ps_t b2v = c_pack[110];
    float b2f, b2d; up2(b2v, b2f, b2d);
    const float c0 = fmaxf(b2f, 0.f);

    ps_t acc[4] = {0ULL, 0ULL, 0ULL, 0ULL};

    // pass A: column q = 32*ww + lane   (base 32*ww)
    sweep_col(32 * ww + lane, 32 * ww, srs[wg], scs[wg], sW[wg], b2v, c0, acc);
    // pass B: column q = 255 - 32*ww - lane (base 224 - 32*ww)
    sweep_col(255 - 32 * ww - lane, 224 - 32 * ww, srs[wg], scs[wg], sW[wg], b2v, c0, acc);

    // reduce acc across lanes, then across the 4 warps of each group
#pragma unroll
    for (int k = 0; k < 4; ++k) {
#pragma unroll
        for (int o = 16; o; o >>= 1)
            acc[k] = add2(acc[k], __shfl_xor_sync(0xffffffffu, acc[k], o));
    }
    if (lane == 0) {
#pragma unroll
        for (int k = 0; k < 4; ++k) sred[w][k] = acc[k];
    }
    __syncthreads();
    if (t < 8) {
        const int g2 = t >> 2, k = t & 3;
        ps_t s = add2(add2(sred[g2 * 4 + 0][k], sred[g2 * 4 + 1][k]),
                      add2(sred[g2 * 4 + 2][k], sred[g2 * 4 + 3][k]));
        float lo, hi; up2(s, lo, hi);
        g_part[(2 * blockIdx.x + g2) * 4 + k] = lo + hi;
    }
}

// ---------------------------------------------------------------------------
// Kernel 3: reduce 256x4 partials + fc2
// ---------------------------------------------------------------------------
__global__ void kfc2(const float* __restrict__ fc1b,
                     const float* __restrict__ fc2w,
                     const float* __restrict__ fc2b,
                     float* __restrict__ out) {
    __shared__ float sh[4];
    const int w = threadIdx.x >> 5;
    const int lane = threadIdx.x & 31;
    float s = 0.f;
    for (int i = lane; i < 256; i += 32) s += g_part[i * 4 + w];
#pragma unroll
    for (int o = 16; o; o >>= 1) s += __shfl_xor_sync(0xffffffffu, s, o);
    if (lane == 0) sh[w] = s;
    __syncthreads();
    if (threadIdx.x == 0) {
        float h0 = fmaxf(sh[0] + fc1b[0], 0.f);
        float h1 = fmaxf(sh[1] + fc1b[1], 0.f);
        float h2 = fmaxf(sh[2] + fc1b[2], 0.f);
        float h3 = fmaxf(sh[3] + fc1b[3], 0.f);
        out[0] = fc2w[0] * h0 + fc2w[1] * h1 + fc2w[2] * h2 + fc2w[3] * h3 + fc2b[0];
        out[1] = fc2w[4] * h0 + fc2w[5] * h1 + fc2w[6] * h2 + fc2w[7] * h3 + fc2b[1];
    }
}

// ---------------------------------------------------------------------------
extern "C" void kernel_launch(void* const* d_in, const int* in_sizes, int n_in,
                              void* d_out, int out_size) {
    const float* x    = (const float*)d_in[0];
    const float* w1   = (const float*)d_in[1];
    const float* b1   = (const float*)d_in[2];
    const float* w2   = (const float*)d_in[3];
    const float* b2   = (const float*)d_in[4];
    const float* fc1w = (const float*)d_in[5];
    const float* fc1b = (const float*)d_in[6];
    const float* fc2w = (const float*)d_in[7];
    const float* fc2b = (const float*)d_in[8];

    ksums<<<NB, 256>>>(x, w1, b1, w2, b2);

    void* gp = nullptr;
    cudaGetSymbolAddress(&gp, g_pack);
    cudaMemcpyToSymbolAsync(c_pack, gp, 111 * sizeof(ps_t), 0,
                            cudaMemcpyDeviceToDevice, 0);

    kband<<<128, 256>>>(fc1w);
    kfc2<<<1, 128>>>(fc1b, fc2w, fc2b, (float*)d_out);
}

// round 5
// speedup vs baseline: 1.4188x; 1.1984x over previous
#include <cuda_runtime.h>
#include <cstdint>

#define NB 512
#define ND 256
#define NC 10

// ---------------------------------------------------------------------------
// packed fp32x2 helpers
// ---------------------------------------------------------------------------
typedef unsigned long long ps_t;

__device__ __forceinline__ ps_t pk2(float lo, float hi) {
    ps_t o; asm("mov.b64 %0,{%1,%2};" : "=l"(o) : "f"(lo), "f"(hi)); return o;
}
__device__ __forceinline__ void up2(ps_t a, float& lo, float& hi) {
    asm("mov.b64 {%0,%1},%2;" : "=f"(lo), "=f"(hi) : "l"(a));
}
__device__ __forceinline__ ps_t fma2(ps_t a, ps_t b, ps_t c) {
    ps_t d; asm("fma.rn.f32x2 %0,%1,%2,%3;" : "=l"(d) : "l"(a), "l"(b), "l"(c)); return d;
}
__device__ __forceinline__ ps_t add2(ps_t a, ps_t b) {
    ps_t d; asm("add.rn.f32x2 %0,%1,%2;" : "=l"(d) : "l"(a), "l"(b)); return d;
}
__device__ __forceinline__ ps_t relu2(ps_t a) {
    float l, h; up2(a, l, h);
    return pk2(fmaxf(l, 0.f), fmaxf(h, 0.f));
}

// packed weights: [0:10) w1, [10:20) b1, [20:110) w2[c*9+kh*3+kw], [110] b2
__constant__ ps_t c_pack[111];
__device__ ps_t g_pack[111];
__device__ float g_part[1024 * 4];
__device__ float g_rs2[NB * ND];   // [pair][i][hb]
__device__ float g_cs2[NB * ND];   // [pair][j][hb]

// ---------------------------------------------------------------------------
// Kernel 1: per-batch row/col sums (streaming). grid=512, 256 threads.
// ---------------------------------------------------------------------------
__global__ void __launch_bounds__(256) ksums(const float* __restrict__ x,
                                             const float* __restrict__ w1,
                                             const float* __restrict__ b1,
                                             const float* __restrict__ w2,
                                             const float* __restrict__ b2) {
    const int b = blockIdx.x;
    const int t = threadIdx.x;
    const int w = t >> 5;
    const int l = t & 31;
    const int bi = b >> 1;
    const int hb = b & 1;

    if (b == 0) {   // weight packing (tiny)
        if (t < 10) { g_pack[t] = pk2(w1[t], w1[t]); g_pack[10 + t] = pk2(b1[t], b1[t]); }
        if (t < 90) g_pack[20 + t] = pk2(w2[t], w2[t]);
        if (t == 0) g_pack[110] = pk2(b2[0], b2[0]);
    }

    __shared__ float scs[8 * 256];
    const float4* __restrict__ xb =
        reinterpret_cast<const float4*>(x + (size_t)b * (ND * ND));

    float ca[8];
#pragma unroll
    for (int k = 0; k < 8; ++k) ca[k] = 0.f;

    const int i0 = 32 * w;
#pragma unroll 4
    for (int ri = 0; ri < 32; ++ri) {
        const int i = i0 + ri;
        float4 v0 = xb[i * 64 + 2 * l];
        float4 v1 = xb[i * 64 + 2 * l + 1];
        ca[0] += v0.x; ca[1] += v0.y; ca[2] += v0.z; ca[3] += v0.w;
        ca[4] += v1.x; ca[5] += v1.y; ca[6] += v1.z; ca[7] += v1.w;
        float rsum = (v0.x + v0.y) + (v0.z + v0.w) + (v1.x + v1.y) + (v1.z + v1.w);
#pragma unroll
        for (int o = 16; o; o >>= 1) rsum += __shfl_xor_sync(0xffffffffu, rsum, o);
        if (l == 0) g_rs2[bi * 512 + i * 2 + hb] = rsum;
    }
#pragma unroll
    for (int k = 0; k < 8; ++k) scs[w * 256 + 8 * l + k] = ca[k];
    __syncthreads();
    float c = 0.f;
#pragma unroll
    for (int ww = 0; ww < 8; ++ww) c += scs[ww * 256 + t];
    g_cs2[bi * 512 + t * 2 + hb] = c;
}

// ---------------------------------------------------------------------------
// tap: 10-ch generate + 3-row accumulate for one conv column e
// ---------------------------------------------------------------------------
__device__ __forceinline__ void tap2(ps_t t2, int e, ps_t& A0, ps_t& A1, ps_t& A2) {
#pragma unroll
    for (int c = 0; c < NC; ++c) {
        ps_t g = relu2(fma2(c_pack[c], t2, c_pack[10 + c]));
        A0 = fma2(c_pack[20 + c * 9 + 0 + e], g, A0);
        A1 = fma2(c_pack[20 + c * 9 + 3 + e], g, A1);
        A2 = fma2(c_pack[20 + c * 9 + 6 + e], g, A2);
    }
}

// ---------------------------------------------------------------------------
// sweep a p-range of column c. Emits rows i=p-1 for p in [emit_from, pend].
// pstart may include 2 warmup iterations to refill the rolling pipeline.
// addcorr: this slice owns the column's start -> add constant-region term.
// ---------------------------------------------------------------------------
__device__ __forceinline__ void run_col(
    int c, int pstart, int pend, int emit_from, bool addcorr,
    const ps_t* __restrict__ srs, const ps_t* __restrict__ scs,
    const ps_t (*__restrict__ sW)[4],
    ps_t b2v, float c0, ps_t acc[4]) {

    ps_t wj[4];
#pragma unroll
    for (int k = 0; k < 4; ++k) wj[k] = sW[c][k];

    const bool vm = (c >= 1);
    const bool vp = (c <= 254);
    const ps_t csm = vm ? scs[c - 1] : 0ULL;
    const ps_t cs0 = scs[c];
    const ps_t csp = vp ? scs[c + 1] : 0ULL;

    ps_t pend1 = 0ULL, a0last = 0ULL, ycol = 0ULL;

    for (int p = pstart; p <= pend; ++p) {
        ps_t A0 = 0ULL, A1 = 0ULL, A2 = 0ULL;
        if (p <= 255) {
            const ps_t rsp = srs[p];
            if (vm && (c - 1) <= p) tap2(add2(rsp, csm), 0, A0, A1, A2);
            if (c <= p)             tap2(add2(rsp, cs0), 1, A0, A1, A2);
            if (vp && (c + 1) <= p) tap2(add2(rsp, csp), 2, A0, A1, A2);
        }
        if (p >= emit_from) {
            ps_t y = relu2(add2(add2(pend1, A2), b2v));
            ps_t yc = (c <= p + 1) ? y : 0ULL;
            ycol = add2(ycol, yc);
            const ps_t* w4 = sW[p - 1];
#pragma unroll
            for (int k = 0; k < 4; ++k) acc[k] = fma2(yc, w4[k], acc[k]);
        }
        pend1 = add2(A1, a0last);
        a0last = A0;
    }

    if (addcorr) {
        const int rn = (253 - c) > 0 ? (253 - c) : 0;
        const int cn = (c - 2) > 0 ? (c - 2) : 0;
        const float cf = c0 * (float)(rn + cn);
        ycol = add2(ycol, pk2(cf, cf));
    }
#pragma unroll
    for (int k = 0; k < 4; ++k) acc[k] = fma2(ycol, wj[k], acc[k]);
}

// ---------------------------------------------------------------------------
// Kernel 2: band conv + fused fc1, sliced 4x in the p-timeline.
// grid = 1024 (= 256 pairs x 4 slices), 128 threads.
// Thread t owns columns (t, 255-t); its constant-length virtual timeline
// (sweep A then sweep B) is cut into 4 equal slices across blocks.
// ---------------------------------------------------------------------------
__global__ void __launch_bounds__(128) kband(const float* __restrict__ fc1w) {
    const int bid = blockIdx.x;
    const int pair = bid >> 2;
    const int s = bid & 3;

    const int t = threadIdx.x;
    const int w = t >> 5;
    const int lane = t & 31;
    const int q = t;                 // low column of the pair (q, 255-q)

    __shared__ ps_t srs[ND];
    __shared__ ps_t scs[ND];
    __shared__ ps_t sW[ND][4];
    __shared__ ps_t sred[4][4];

#pragma unroll
    for (int r = 0; r < 2; ++r) {
        const int i = t + 128 * r;
        srs[i] = ((const ps_t*)g_rs2)[pair * 256 + i];
        scs[i] = ((const ps_t*)g_cs2)[pair * 256 + i];
    }
    const int b0 = 2 * pair;
    for (int idx = t; idx < 1024; idx += 128) {
        const int i = idx >> 2, k = idx & 3;
        sW[i][k] = pk2(fc1w[(size_t)k * 131072 + b0 * 256 + i],
                       fc1w[(size_t)k * 131072 + (b0 + 1) * 256 + i]);
    }
    __syncthreads();

    const ps_t b2v = c_pack[110];
    float b2f, b2d; up2(b2v, b2f, b2d);
    const float c0 = fmaxf(b2f, 0.f);

    ps_t acc[4] = {0ULL, 0ULL, 0ULL, 0ULL};

    // virtual timeline: part A = col q over p in [pA0, 256]; part B = col 255-q
    const int pA0 = (q - 3 > 0) ? (q - 3) : 0;
    const int iterA = 257 - pA0;
    const int iterB = q + 5;           // pB0 = 252 - q
    const int tot = iterA + iterB;
    const int v0 = (tot * s) >> 2;
    const int v1 = (tot * (s + 1)) >> 2;

    // part A overlap [v0, min(v1, iterA))
    {
        const int a0 = v0;
        const int a1 = (v1 < iterA) ? v1 : iterA;
        if (a0 < a1) {
            const int pbeg = pA0 + a0;
            const int pend = pA0 + a1 - 1;
            const int pstart = (a0 == 0) ? pbeg : ((pbeg - 2 > 0) ? pbeg - 2 : 0);
            const int ef = (pbeg > 1) ? pbeg : 1;
            run_col(q, pstart, pend, ef, a0 == 0, srs, scs, sW, b2v, c0, acc);
        }
    }
    // part B overlap [max(v0, iterA), v1)
    {
        const int u0 = (v0 > iterA) ? (v0 - iterA) : 0;
        const int u1 = v1 - iterA;
        if (u1 > u0) {
            const int pB0 = 252 - q;
            const int pbeg = pB0 + u0;
            const int pend = pB0 + u1 - 1;
            const int pstart = (u0 == 0) ? pbeg : ((pbeg - 2 > 0) ? pbeg - 2 : 0);
            const int ef = (pbeg > 1) ? pbeg : 1;
            run_col(255 - q, pstart, pend, ef, u0 == 0, srs, scs, sW, b2v, c0, acc);
        }
    }

    // reduce acc across lanes, then across the 4 warps
#pragma unroll
    for (int k = 0; k < 4; ++k) {
#pragma unroll
        for (int o = 16; o; o >>= 1)
            acc[k] = add2(acc[k], __shfl_xor_sync(0xffffffffu, acc[k], o));
    }
    if (lane == 0) {
#pragma unroll
        for (int k = 0; k < 4; ++k) sred[w][k] = acc[k];
    }
    __syncthreads();
    if (t < 4) {
        ps_t sv = add2(add2(sred[0][t], sred[1][t]), add2(sred[2][t], sred[3][t]));
        float lo, hi; up2(sv, lo, hi);
        g_part[bid * 4 + t] = lo + hi;
    }
}

// ---------------------------------------------------------------------------
// Kernel 3: reduce 1024x4 partials + fc2
// ---------------------------------------------------------------------------
__global__ void kfc2(const float* __restrict__ fc1b,
                     const float* __restrict__ fc2w,
                     const float* __restrict__ fc2b,
                     float* __restrict__ out) {
    __shared__ float sh[4];
    const int w = threadIdx.x >> 5;
    const int lane = threadIdx.x & 31;
    float s = 0.f;
    for (int i = lane; i < 1024; i += 32) s += g_part[i * 4 + w];
#pragma unroll
    for (int o = 16; o; o >>= 1) s += __shfl_xor_sync(0xffffffffu, s, o);
    if (lane == 0) sh[w] = s;
    __syncthreads();
    if (threadIdx.x == 0) {
        float h0 = fmaxf(sh[0] + fc1b[0], 0.f);
        float h1 = fmaxf(sh[1] + fc1b[1], 0.f);
        float h2 = fmaxf(sh[2] + fc1b[2], 0.f);
        float h3 = fmaxf(sh[3] + fc1b[3], 0.f);
        out[0] = fc2w[0] * h0 + fc2w[1] * h1 + fc2w[2] * h2 + fc2w[3] * h3 + fc2b[0];
        out[1] = fc2w[4] * h0 + fc2w[5] * h1 + fc2w[6] * h2 + fc2w[7] * h3 + fc2b[1];
    }
}

// ---------------------------------------------------------------------------
extern "C" void kernel_launch(void* const* d_in, const int* in_sizes, int n_in,
                              void* d_out, int out_size) {
    const float* x    = (const float*)d_in[0];
    const float* w1   = (const float*)d_in[1];
    const float* b1   = (const float*)d_in[2];
    const float* w2   = (const float*)d_in[3];
    const float* b2   = (const float*)d_in[4];
    const float* fc1w = (const float*)d_in[5];
    const float* fc1b = (const float*)d_in[6];
    const float* fc2w = (const float*)d_in[7];
    const float* fc2b = (const float*)d_in[8];

    ksums<<<NB, 256>>>(x, w1, b1, w2, b2);

    void* gp = nullptr;
    cudaGetSymbolAddress(&gp, g_pack);
    cudaMemcpyToSymbolAsync(c_pack, gp, 111 * sizeof(ps_t), 0,
                            cudaMemcpyDeviceToDevice, 0);

    kband<<<1024, 128>>>(fc1w);
    kfc2<<<1, 128>>>(fc1b, fc2w, fc2b, (float*)d_out);
}